// round 9
// baseline (speedup 1.0000x reference)
#include <cuda_runtime.h>
#include <cuda_fp16.h>
#include <math.h>
#include <stdint.h>

#define BB 2
#define NN 2048
#define CC 1024
#define HH 16
#define DD 64
#define FF 4096
#define RR (BB*NN)   // 4096 rows

// ---------------- scratch ----------------
__device__ __align__(16) __half g_xn   [(size_t)RR*CC];
__device__ __align__(16) __half g_qkv  [(size_t)RR*3*CC];
__device__ __align__(16) __half g_y    [(size_t)RR*CC];
__device__ __align__(16) float  g_x2   [(size_t)RR*CC];
__device__ __align__(16) __half g_hb   [(size_t)RR*FF];
__device__ __align__(16) __half g_Wqkvt[(size_t)3*CC*CC];
__device__ __align__(16) __half g_Wpt  [(size_t)CC*CC];
__device__ __align__(16) __half g_W1t  [(size_t)FF*CC];
__device__ __align__(16) __half g_W2t  [(size_t)CC*FF];

// ---------------- helpers ----------------
__device__ __forceinline__ uint32_t smem_u32(const void* p) {
    uint32_t a;
    asm("{ .reg .u64 t; cvta.to.shared.u64 t, %1; cvt.u32.u64 %0, t; }" : "=r"(a) : "l"(p));
    return a;
}
__device__ __forceinline__ void cp16(uint32_t s, const void* g) {
    asm volatile("cp.async.cg.shared.global [%0], [%1], 16;" :: "r"(s), "l"(g));
}
__device__ __forceinline__ void cp_commit() { asm volatile("cp.async.commit_group;" ::: "memory"); }
__device__ __forceinline__ void cp_wait1()  { asm volatile("cp.async.wait_group 1;" ::: "memory"); }
__device__ __forceinline__ void cp_wait0()  { asm volatile("cp.async.wait_group 0;" ::: "memory"); }

__device__ __forceinline__ void ldmx4(uint32_t& r0, uint32_t& r1, uint32_t& r2, uint32_t& r3, uint32_t a) {
    asm volatile("ldmatrix.sync.aligned.m8n8.x4.shared.b16 {%0,%1,%2,%3}, [%4];"
                 : "=r"(r0), "=r"(r1), "=r"(r2), "=r"(r3) : "r"(a));
}
__device__ __forceinline__ void ldmx2(uint32_t& r0, uint32_t& r1, uint32_t a) {
    asm volatile("ldmatrix.sync.aligned.m8n8.x2.shared.b16 {%0,%1}, [%2];"
                 : "=r"(r0), "=r"(r1) : "r"(a));
}
__device__ __forceinline__ void ldmx2t(uint32_t& r0, uint32_t& r1, uint32_t a) {
    asm volatile("ldmatrix.sync.aligned.m8n8.x2.trans.shared.b16 {%0,%1}, [%2];"
                 : "=r"(r0), "=r"(r1) : "r"(a));
}
__device__ __forceinline__ void mma_h(float* d, uint32_t a0, uint32_t a1, uint32_t a2, uint32_t a3,
                                      uint32_t b0, uint32_t b1) {
    asm volatile(
        "mma.sync.aligned.m16n8k16.row.col.f32.f16.f16.f32 "
        "{%0,%1,%2,%3}, {%4,%5,%6,%7}, {%8,%9}, {%0,%1,%2,%3};"
        : "+f"(d[0]), "+f"(d[1]), "+f"(d[2]), "+f"(d[3])
        : "r"(a0), "r"(a1), "r"(a2), "r"(a3), "r"(b0), "r"(b1));
}

// ---------------- layernorm (fp32 in, fp16 out) ----------------
__global__ void layernorm_kernel(const float* __restrict__ x,
                                 const float* __restrict__ gamma,
                                 const float* __restrict__ beta,
                                 __half* __restrict__ out) {
    __shared__ float red[256];
    int row = blockIdx.x;
    const float* xr = x + (size_t)row * CC;
    __half* orow = out + (size_t)row * CC;
    int t = threadIdx.x;

    float s = 0.f;
    for (int i = t; i < CC; i += 256) s += xr[i];
    red[t] = s; __syncthreads();
    for (int st = 128; st > 0; st >>= 1) { if (t < st) red[t] += red[t + st]; __syncthreads(); }
    float mu = red[0] / (float)CC;
    __syncthreads();

    float v = 0.f;
    for (int i = t; i < CC; i += 256) { float d = xr[i] - mu; v += d * d; }
    red[t] = v; __syncthreads();
    for (int st = 128; st > 0; st >>= 1) { if (t < st) red[t] += red[t + st]; __syncthreads(); }
    float inv = rsqrtf(red[0] / (float)CC + 1e-6f);

    for (int i = t; i < CC; i += 256)
        orow[i] = __float2half_rn((xr[i] - mu) * inv * gamma[i] + beta[i]);
}

// ---------------- fused weight prep: all six transposes in one launch ----------------
__global__ void weight_prep_kernel(const float* Wq, const float* Wk, const float* Wv,
                                   const float* Wp, const float* W1, const float* W2,
                                   __half* Wqkvt, __half* Wpt, __half* W1t, __half* W2t) {
    __shared__ float tile[32][33];
    int id = blockIdx.x;
    const float* in; long ldi; __half* out; long ldo; float alpha = 1.f; int bx, by;

    if (id < 4096) {
        int seg = id >> 10, loc = id & 1023;
        bx = loc & 31; by = loc >> 5;
        ldi = CC; ldo = CC;
        if (seg == 0)      { in = Wq; out = Wqkvt;                     alpha = 0.125f; }
        else if (seg == 1) { in = Wk; out = Wqkvt + (size_t)CC*CC;   }
        else if (seg == 2) { in = Wv; out = Wqkvt + (size_t)2*CC*CC; }
        else               { in = Wp; out = Wpt; }
    } else if (id < 8192) {
        int loc = id - 4096;
        bx = loc & 127; by = loc >> 7;           // (FF/32) x (CC/32)
        in = W1; ldi = FF; out = W1t; ldo = CC;
    } else {
        int loc = id - 8192;
        bx = loc & 31; by = loc >> 5;            // (CC/32) x (FF/32)
        in = W2; ldi = CC; out = W2t; ldo = FF;
    }

    int c0 = bx * 32, r0 = by * 32;
    int tx = threadIdx.x, ty = threadIdx.y;      // 32 x 8
    #pragma unroll
    for (int i = 0; i < 32; i += 8)
        tile[ty + i][tx] = in[(long)(r0 + ty + i) * ldi + (c0 + tx)];
    __syncthreads();
    #pragma unroll
    for (int i = 0; i < 32; i += 8)
        out[(long)(c0 + ty + i) * ldo + (r0 + tx)] = __float2half_rn(tile[tx][ty + i] * alpha);
}

// ---------------- fp16 mma GEMM, 128x256 block, 64x64 warp tiles ----------------
#define G_SS 40
#define G_ASZ (128 * G_SS)
#define G_BSZ (256 * G_SS)
#define G_SMEM ((2 * G_ASZ + 2 * G_BSZ) * 2)

template<bool GELU_, bool HOUT>
__global__ void __launch_bounds__(256) hgemm2(
    int K,
    const __half* __restrict__ A, long lda,
    const __half* __restrict__ B, long ldb,
    void* __restrict__ Cv, long ldc,
    const float* __restrict__ bias,
    const float* __restrict__ resid, long ldr)
{
    extern __shared__ __half sh[];
    uint32_t asb = smem_u32(sh);
    uint32_t bsb = asb + 2 * G_ASZ * 2;

    int tid = threadIdx.x;
    int wid = tid >> 5, lane = tid & 31;
    int wrow = wid >> 2, wcol = wid & 3;          // 2 x 4 warps
    int r = lane >> 2, c = lane & 3;
    int mb = wrow * 64, nb = wcol * 64;
    int l7 = lane & 7, l8 = lane & 8, lh = (lane >> 4) << 3;

    const __half* Ag = A + (long)(blockIdx.y * 128) * lda;
    const __half* Bg = B + (long)(blockIdx.x * 256) * ldb;
    const int nk = K / 32;

    auto load_chunk = [&](int i, int s) {
        long k0 = (long)i * 32;
        uint32_t ad = asb + s * G_ASZ * 2;
        #pragma unroll
        for (int t = tid; t < 512; t += 256) {
            int m = t >> 2, ch = t & 3;
            cp16(ad + (m * G_SS + ch * 8) * 2, Ag + (long)m * lda + k0 + ch * 8);
        }
        uint32_t bd = bsb + s * G_BSZ * 2;
        #pragma unroll
        for (int t = tid; t < 1024; t += 256) {
            int n = t >> 2, ch = t & 3;
            cp16(bd + (n * G_SS + ch * 8) * 2, Bg + (long)n * ldb + k0 + ch * 8);
        }
        cp_commit();
    };

    float acc[4][8][4];
    #pragma unroll
    for (int i = 0; i < 4; i++)
        #pragma unroll
        for (int j = 0; j < 8; j++)
            #pragma unroll
            for (int e = 0; e < 4; e++) acc[i][j][e] = 0.f;

    load_chunk(0, 0);

    for (int it = 0; it < nk; it++) {
        int s = it & 1;
        if (it + 1 < nk) { load_chunk(it + 1, s ^ 1); cp_wait1(); } else { cp_wait0(); }
        __syncthreads();

        uint32_t as = asb + s * G_ASZ * 2;
        uint32_t bs = bsb + s * G_BSZ * 2;
        #pragma unroll
        for (int kk = 0; kk < 32; kk += 16) {
            uint32_t bf[8][2];
            #pragma unroll
            for (int j = 0; j < 8; j++)
                ldmx2(bf[j][0], bf[j][1], bs + ((nb + j * 8 + l7) * G_SS + kk + l8) * 2);
            #pragma unroll
            for (int i = 0; i < 4; i++) {
                uint32_t a0, a1, a2, a3;
                ldmx4(a0, a1, a2, a3, as + ((mb + i * 16 + l7 + l8) * G_SS + kk + lh) * 2);
                #pragma unroll
                for (int j = 0; j < 8; j++)
                    mma_h(acc[i][j], a0, a1, a2, a3, bf[j][0], bf[j][1]);
            }
        }
        __syncthreads();
    }

    long row0 = (long)blockIdx.y * 128 + mb;
    long col0 = (long)blockIdx.x * 256 + nb;
    #pragma unroll
    for (int i = 0; i < 4; i++) {
        #pragma unroll
        for (int j = 0; j < 8; j++) {
            long gcol = col0 + j * 8 + 2 * c;
            #pragma unroll
            for (int half_ = 0; half_ < 2; half_++) {
                long grow = row0 + i * 16 + r + half_ * 8;
                float vx = acc[i][j][half_ * 2 + 0];
                float vy = acc[i][j][half_ * 2 + 1];
                if (bias) { vx += bias[gcol]; vy += bias[gcol + 1]; }
                if (GELU_) {
                    vx = 0.5f * vx * (1.f + erff(vx * 0.70710678118654752f));
                    vy = 0.5f * vy * (1.f + erff(vy * 0.70710678118654752f));
                }
                if (resid) {
                    const float2 rr = *reinterpret_cast<const float2*>(resid + grow * ldr + gcol);
                    vx += rr.x; vy += rr.y;
                }
                if (HOUT) {
                    *reinterpret_cast<__half2*>((__half*)Cv + grow * ldc + gcol) =
                        __floats2half2_rn(vx, vy);
                } else {
                    float2 o; o.x = vx; o.y = vy;
                    *reinterpret_cast<float2*>((float*)Cv + grow * ldc + gcol) = o;
                }
            }
        }
    }
}

// ---------------- flash attention (fp16 operands, fp32 softmax/accum) ----------------
#define QS 72
#define KS 72
#define VS 72
#define PS 72
#define FLASH_SMEM ((128*QS + 2*64*KS + 2*64*VS + 128*PS) * 2)

__global__ void __launch_bounds__(256) flash_kernel(const __half* __restrict__ qkv,
                                                    __half* __restrict__ y) {
    extern __shared__ __half fsh[];
    __half* Qs = fsh;
    __half* Ks = Qs + 128 * QS;
    __half* Vs = Ks + 2 * 64 * KS;
    __half* Ps = Vs + 2 * 64 * VS;

    int tid = threadIdx.x;
    int wid = tid >> 5, lane = tid & 31;
    int r = lane >> 2, c = lane & 3;
    int mb = wid * 16;
    int l7 = lane & 7, l8 = lane & 8, lh = (lane >> 4) << 3;

    int bh = blockIdx.y;
    int b = bh >> 4, h = bh & 15;
    long qrow0 = (long)b * NN + (long)blockIdx.x * 128;
    long kvrow0 = (long)b * NN;
    const __half* qg = qkv + qrow0 * 3072 + h * 64;
    const __half* kg = qkv + kvrow0 * 3072 + 1024 + h * 64;
    const __half* vg = qkv + kvrow0 * 3072 + 2048 + h * 64;

    uint32_t qsb = smem_u32(Qs), ksb = smem_u32(Ks), vsb = smem_u32(Vs), psb = smem_u32(Ps);

    #pragma unroll
    for (int t = tid; t < 1024; t += 256) {
        int row = t >> 3, ch = t & 7;
        cp16(qsb + (row * QS + ch * 8) * 2, qg + (long)row * 3072 + ch * 8);
    }
    cp_commit();

    auto load_kv = [&](int i, int s) {
        long rb = (long)i * 64;
        #pragma unroll
        for (int t = tid; t < 512; t += 256) {
            int row = t >> 3, ch = t & 7;
            cp16(ksb + ((s * 64 + row) * KS + ch * 8) * 2, kg + (rb + row) * 3072 + ch * 8);
        }
        #pragma unroll
        for (int t = tid; t < 512; t += 256) {
            int row = t >> 3, ch = t & 7;
            cp16(vsb + ((s * 64 + row) * VS + ch * 8) * 2, vg + (rb + row) * 3072 + ch * 8);
        }
        cp_commit();
    };

    load_kv(0, 0);

    float m0 = -1e30f, m1 = -1e30f, l0 = 0.f, l1 = 0.f;
    float o[8][4];
    #pragma unroll
    for (int j = 0; j < 8; j++)
        #pragma unroll
        for (int e = 0; e < 4; e++) o[j][e] = 0.f;

    const int niter = NN / 64;
    for (int it = 0; it < niter; it++) {
        int s = it & 1;
        if (it + 1 < niter) { load_kv(it + 1, s ^ 1); cp_wait1(); } else { cp_wait0(); }
        __syncthreads();

        float sacc[8][4];
        #pragma unroll
        for (int j = 0; j < 8; j++)
            #pragma unroll
            for (int e = 0; e < 4; e++) sacc[j][e] = 0.f;

        uint32_t ks = ksb + s * 64 * KS * 2;
        #pragma unroll
        for (int kk = 0; kk < 64; kk += 16) {
            uint32_t a0, a1, a2, a3;
            ldmx4(a0, a1, a2, a3, qsb + ((mb + l7 + l8) * QS + kk + lh) * 2);
            #pragma unroll
            for (int j = 0; j < 8; j++) {
                uint32_t b0, b1;
                ldmx2(b0, b1, ks + ((j * 8 + l7) * KS + kk + l8) * 2);
                mma_h(sacc[j], a0, a1, a2, a3, b0, b1);
            }
        }

        float mx0 = -1e30f, mx1 = -1e30f;
        #pragma unroll
        for (int j = 0; j < 8; j++) {
            mx0 = fmaxf(mx0, fmaxf(sacc[j][0], sacc[j][1]));
            mx1 = fmaxf(mx1, fmaxf(sacc[j][2], sacc[j][3]));
        }
        #pragma unroll
        for (int off = 1; off <= 2; off <<= 1) {
            mx0 = fmaxf(mx0, __shfl_xor_sync(0xffffffffu, mx0, off));
            mx1 = fmaxf(mx1, __shfl_xor_sync(0xffffffffu, mx1, off));
        }
        float mn0 = fmaxf(m0, mx0), mn1 = fmaxf(m1, mx1);
        float sc0 = __expf(m0 - mn0), sc1 = __expf(m1 - mn1);
        float sum0 = 0.f, sum1 = 0.f;
        #pragma unroll
        for (int j = 0; j < 8; j++) {
            float e0 = __expf(sacc[j][0] - mn0);
            float e1 = __expf(sacc[j][1] - mn0);
            float e2 = __expf(sacc[j][2] - mn1);
            float e3 = __expf(sacc[j][3] - mn1);
            sum0 += e0 + e1; sum1 += e2 + e3;
            *reinterpret_cast<__half2*>(&Ps[(mb + r) * PS + j * 8 + 2 * c]) = __floats2half2_rn(e0, e1);
            *reinterpret_cast<__half2*>(&Ps[(mb + r + 8) * PS + j * 8 + 2 * c]) = __floats2half2_rn(e2, e3);
        }
        #pragma unroll
        for (int off = 1; off <= 2; off <<= 1) {
            sum0 += __shfl_xor_sync(0xffffffffu, sum0, off);
            sum1 += __shfl_xor_sync(0xffffffffu, sum1, off);
        }
        l0 = l0 * sc0 + sum0;
        l1 = l1 * sc1 + sum1;
        m0 = mn0; m1 = mn1;
        #pragma unroll
        for (int j = 0; j < 8; j++) {
            o[j][0] *= sc0; o[j][1] *= sc0; o[j][2] *= sc1; o[j][3] *= sc1;
        }
        __syncwarp();

        uint32_t vs = vsb + s * 64 * VS * 2;
        #pragma unroll
        for (int kk = 0; kk < 64; kk += 16) {
            uint32_t a0, a1, a2, a3;
            ldmx4(a0, a1, a2, a3, psb + ((mb + l7 + l8) * PS + kk + lh) * 2);
            #pragma unroll
            for (int j = 0; j < 8; j++) {
                uint32_t b0, b1;
                ldmx2t(b0, b1, vs + ((kk + l7 + l8) * VS + j * 8) * 2);
                mma_h(o[j], a0, a1, a2, a3, b0, b1);
            }
        }
        __syncwarp();
        __syncthreads();
    }

    float inv0 = 1.f / l0, inv1 = 1.f / l1;
    long grow0 = qrow0 + mb + r;
    long grow1 = grow0 + 8;
    #pragma unroll
    for (int j = 0; j < 8; j++) {
        long gcol = h * 64 + j * 8 + 2 * c;
        *reinterpret_cast<__half2*>(y + grow0 * CC + gcol) =
            __floats2half2_rn(o[j][0] * inv0, o[j][1] * inv0);
        *reinterpret_cast<__half2*>(y + grow1 * CC + gcol) =
            __floats2half2_rn(o[j][2] * inv1, o[j][3] * inv1);
    }
}

// ---------------- host ----------------
template<typename T>
static T* sym_addr(const void* s) {
    void* p = nullptr;
    cudaGetSymbolAddress(&p, s);
    return (T*)p;
}

extern "C" void kernel_launch(void* const* d_in, const int* in_sizes, int n_in,
                              void* d_out, int out_size) {
    const float* x      = (const float*)d_in[0];
    const float* Wq     = (const float*)d_in[1];
    const float* Wk     = (const float*)d_in[2];
    const float* Wv     = (const float*)d_in[3];
    const float* Wp     = (const float*)d_in[4];
    const float* bp     = (const float*)d_in[5];
    const float* W1     = (const float*)d_in[6];
    const float* b1     = (const float*)d_in[7];
    const float* W2     = (const float*)d_in[8];
    const float* b2     = (const float*)d_in[9];
    const float* gamma1 = (const float*)d_in[10];
    const float* beta1  = (const float*)d_in[11];
    const float* gamma2 = (const float*)d_in[12];
    const float* beta2  = (const float*)d_in[13];
    float* out = (float*)d_out;

    __half* xn    = sym_addr<__half>(g_xn);
    __half* qkv   = sym_addr<__half>(g_qkv);
    __half* y     = sym_addr<__half>(g_y);
    float*  x2    = sym_addr<float >(g_x2);
    __half* hb    = sym_addr<__half>(g_hb);
    __half* Wqkvt = sym_addr<__half>(g_Wqkvt);
    __half* Wpt   = sym_addr<__half>(g_Wpt);
    __half* W1t   = sym_addr<__half>(g_W1t);
    __half* W2t   = sym_addr<__half>(g_W2t);

    cudaFuncSetAttribute(flash_kernel, cudaFuncAttributeMaxDynamicSharedMemorySize, FLASH_SMEM);
    cudaFuncSetAttribute(hgemm2<false, true >, cudaFuncAttributeMaxDynamicSharedMemorySize, G_SMEM);
    cudaFuncSetAttribute(hgemm2<false, false>, cudaFuncAttributeMaxDynamicSharedMemorySize, G_SMEM);
    cudaFuncSetAttribute(hgemm2<true,  true >, cudaFuncAttributeMaxDynamicSharedMemorySize, G_SMEM);

    // fused weight prep (6 transposes, one launch)
    weight_prep_kernel<<<12288, dim3(32, 8)>>>(Wq, Wk, Wv, Wp, W1, W2, Wqkvt, Wpt, W1t, W2t);

    // LN1 -> fp16
    layernorm_kernel<<<RR, 256>>>(x, gamma1, beta1, xn);

    // fused QKV: [4096, 3072] fp16
    hgemm2<false, true><<<dim3(3*CC/256, RR/128), 256, G_SMEM>>>(CC,
        xn, CC, Wqkvt, CC, qkv, 3*CC, nullptr, nullptr, 0);

    // flash attention -> y fp16
    flash_kernel<<<dim3(NN/128, BB*HH), 256, FLASH_SMEM>>>(qkv, y);

    // x2 = x + y @ Wp + bp   (fp32 out)
    hgemm2<false, false><<<dim3(CC/256, RR/128), 256, G_SMEM>>>(CC,
        y, CC, Wpt, CC, x2, CC, bp, x, CC);

    // LN2 -> fp16
    layernorm_kernel<<<RR, 256>>>(x2, gamma2, beta2, xn);

    // hb = fp16(gelu(xn @ W1 + b1))
    hgemm2<true, true><<<dim3(FF/256, RR/128), 256, G_SMEM>>>(CC,
        xn, CC, W1t, CC, hb, FF, b1, nullptr, 0);

    // out = x2 + hb @ W2 + b2  (fp32 out)
    hgemm2<false, false><<<dim3(CC/256, RR/128), 256, G_SMEM>>>(FF,
        hb, FF, W2t, FF, out, CC, b2, x2, CC);
}